// round 16
// baseline (speedup 1.0000x reference)
#include <cuda_runtime.h>
#include <cuda_bf16.h>
#include <math.h>
#include <stdint.h>

#define EMB     2048
#define S_LEN   2048
#define B_SZ    2
#define HEADS   16
#define HDIM    128
#define QKV_N   (3*EMB)
#define MROWS   (B_SZ*S_LEN)

// ---------------- scratch ----------------
__device__ float          g_qkv[25165824];      // 4096 x 6144 fp32 (GEMM1 out)
__device__ __nv_bfloat16  g_qkvh[25165824];     // rope'd+split qkv hi
__device__ __nv_bfloat16  g_qkvl[25165824];     // lo
__device__ __nv_bfloat16  g_ah[8388608];        // A hi (x / attn-out)
__device__ __nv_bfloat16  g_al[8388608];        // A lo
__device__ __nv_bfloat16  g_bh[12582912];       // B hi (w_qkv / w_out)
__device__ __nv_bfloat16  g_bl[12582912];       // B lo
__device__ float  g_cos[S_LEN*64];
__device__ float  g_sin[S_LEN*64];
__device__ float  g_colpart[B_SZ*8*EMB];
__device__ double g_psum[128];
__device__ double g_psq[128];
__device__ int    g_window;

#define QSCALE 0.08838834764831845f

__device__ __forceinline__ uint32_t smem_u32(const void* p) {
    uint32_t a;
    asm("{ .reg .u64 t; cvta.to.shared.u64 t, %1; cvt.u32.u64 %0, t; }" : "=r"(a) : "l"(p));
    return a;
}
__device__ __forceinline__ void ldsm_x4(uint32_t* r, uint32_t addr) {
    asm volatile("ldmatrix.sync.aligned.m8n8.x4.shared.b16 {%0,%1,%2,%3}, [%4];"
        : "=r"(r[0]), "=r"(r[1]), "=r"(r[2]), "=r"(r[3]) : "r"(addr));
}
__device__ __forceinline__ void ldsm_x4_t(uint32_t* r, uint32_t addr) {
    asm volatile("ldmatrix.sync.aligned.m8n8.x4.trans.shared.b16 {%0,%1,%2,%3}, [%4];"
        : "=r"(r[0]), "=r"(r[1]), "=r"(r[2]), "=r"(r[3]) : "r"(addr));
}
__device__ __forceinline__ void mma16816(float* c, const uint32_t* a, uint32_t b0, uint32_t b1) {
    asm volatile("mma.sync.aligned.m16n8k16.row.col.f32.bf16.bf16.f32 "
        "{%0,%1,%2,%3}, {%4,%5,%6,%7}, {%8,%9}, {%0,%1,%2,%3};"
        : "+f"(c[0]), "+f"(c[1]), "+f"(c[2]), "+f"(c[3])
        : "r"(a[0]), "r"(a[1]), "r"(a[2]), "r"(a[3]), "r"(b0), "r"(b1));
}
__device__ __forceinline__ void split2(float x, float y, uint32_t& hi, uint32_t& lo) {
    __nv_bfloat16 hx = __float2bfloat16(x);
    __nv_bfloat16 hy = __float2bfloat16(y);
    __nv_bfloat162 h2 = __halves2bfloat162(hx, hy);
    __nv_bfloat162 l2 = __halves2bfloat162(
        __float2bfloat16(x - __bfloat162float(hx)),
        __float2bfloat16(y - __bfloat162float(hy)));
    hi = *(uint32_t*)&h2;
    lo = *(uint32_t*)&l2;
}

// ---------------- small kernels ----------------
__global__ void rope_table_kernel() {
    int idx = blockIdx.x * blockDim.x + threadIdx.x;
    if (idx >= S_LEN * 64) return;
    int s = idx >> 6, j = idx & 63;
    double inf = exp(-((double)j) * (9.210340371976184 / 64.0));
    double sp, cp;
    sincos((double)s * inf, &sp, &cp);
    g_cos[idx] = (float)cp;
    g_sin[idx] = (float)sp;
}

__global__ void stats_kernel(const float* __restrict__ x) {
    __shared__ double sd[256];
    int t = threadIdx.x;
    int e = blockIdx.x * 256 + t;
    int b = blockIdx.z;
    const float* p = x + ((size_t)(b * S_LEN + blockIdx.y * 256)) * EMB + e;
    float cs = 0.f;
    double ds = 0.0, dq = 0.0;
#pragma unroll 4
    for (int i = 0; i < 256; i++) {
        float v = p[(size_t)i * EMB];
        cs += v;
        ds += (double)v;
        dq += (double)v * (double)v;
    }
    g_colpart[(b * 8 + blockIdx.y) * EMB + e] = cs;
    sd[t] = ds; __syncthreads();
    for (int o = 128; o > 0; o >>= 1) { if (t < o) sd[t] += sd[t + o]; __syncthreads(); }
    double tot = sd[0]; __syncthreads();
    sd[t] = dq; __syncthreads();
    for (int o = 128; o > 0; o >>= 1) { if (t < o) sd[t] += sd[t + o]; __syncthreads(); }
    if (t == 0) {
        int bi = b * 64 + blockIdx.y * 8 + blockIdx.x;
        g_psum[bi] = tot;
        g_psq[bi]  = sd[0];
    }
}

__global__ void window_kernel(const float* __restrict__ w_c1, const float* __restrict__ w_c2) {
    __shared__ float  xm[2 * EMB];
    __shared__ float  red[512];
    __shared__ double dred[64];
    __shared__ float  varn[2];
    __shared__ float  lgv[2];
    int t = threadIdx.x;

    for (int idx = t; idx < 2 * EMB; idx += 512) {
        int b = idx >> 11, e = idx & 2047;
        float s = 0.f;
#pragma unroll
        for (int c = 0; c < 8; c++) s += g_colpart[(b * 8 + c) * EMB + e];
        xm[idx] = s * (1.0f / (float)S_LEN);
    }

    for (int b = 0; b < 2; b++) {
        __syncthreads();
        if (t < 64) dred[t] = g_psum[b * 64 + t];
        __syncthreads();
        for (int o = 32; o > 0; o >>= 1) { if (t < o) dred[t] += dred[t + o]; __syncthreads(); }
        double sum = dred[0];
        __syncthreads();
        if (t < 64) dred[t] = g_psq[b * 64 + t];
        __syncthreads();
        for (int o = 32; o > 0; o >>= 1) { if (t < o) dred[t] += dred[t + o]; __syncthreads(); }
        if (t == 0) {
            double N = (double)S_LEN * (double)EMB;
            float v = (float)((dred[0] - sum * sum / N) / (N - 1.0));
            varn[b] = 1.0f / (1.0f + expf(-(v * 10.0f - 5.0f)));
        }
    }
    __syncthreads();

    float acc0 = 0.f, acc1 = 0.f;
    const float* wr = w_c1 + (size_t)t * EMB;
    for (int e = 0; e < EMB; e++) {
        float w = wr[e];
        acc0 = fmaf(xm[e], w, acc0);
        acc1 = fmaf(xm[EMB + e], w, acc1);
    }
    float w2 = w_c2[t];
    float h0 = acc0 / (1.0f + expf(-acc0));
    float h1 = acc1 / (1.0f + expf(-acc1));

    red[t] = h0 * w2; __syncthreads();
    for (int o = 256; o > 0; o >>= 1) { if (t < o) red[t] += red[t + o]; __syncthreads(); }
    if (t == 0) lgv[0] = red[0];
    __syncthreads();
    red[t] = h1 * w2; __syncthreads();
    for (int o = 256; o > 0; o >>= 1) { if (t < o) red[t] += red[t + o]; __syncthreads(); }
    if (t == 0) {
        lgv[1] = red[0];
        float l0 = 1.0f / (1.0f + expf(-lgv[0]));
        float l1 = 1.0f / (1.0f + expf(-lgv[1]));
        float wf0 = 64.0f + 0.5f * (varn[0] + l0) * 192.0f;
        float wf1 = 64.0f + 0.5f * (varn[1] + l1) * 192.0f;
        int win = (int)(0.5f * (wf0 + wf1));
        if (win > S_LEN) win = S_LEN;
        if (win < 64) win = 64;
        g_window = win;
    }
}

__global__ void split_kernel(const float* __restrict__ src,
                             __nv_bfloat16* __restrict__ hi,
                             __nv_bfloat16* __restrict__ lo, int n4) {
    int i = blockIdx.x * blockDim.x + threadIdx.x;
    if (i >= n4) return;
    float4 v = ((const float4*)src)[i];
    uint32_t h0, l0, h1, l1;
    split2(v.x, v.y, h0, l0);
    split2(v.z, v.w, h1, l1);
    uint2* hp = (uint2*)hi;
    uint2* lp = (uint2*)lo;
    uint2 a; a.x = h0; a.y = h1; hp[i] = a;
    a.x = l0; a.y = l1; lp[i] = a;
}

// rope + q-scale + bf16 hi/lo split over the whole qkv buffer (one pass)
__global__ void qkv_rope_split_kernel() {
    int idx = blockIdx.x * blockDim.x + threadIdx.x;   // one float4 each
    int row = idx / (QKV_N / 4);
    int c4  = (idx % (QKV_N / 4)) * 4;
    float4 v = *(const float4*)(g_qkv + (size_t)row * QKV_N + c4);
    float vals[4] = {v.x, v.y, v.z, v.w};
    int part = c4 >> 11;                 // 0=q, 1=k, 2=v
    if (part < 2) {
        int s = row & (S_LEN - 1);
        int d = c4 & 127;
#pragma unroll
        for (int pp = 0; pp < 2; pp++) {
            int j0 = (d + 2 * pp) & 63;
            float c0 = g_cos[s * 64 + j0],     sn0 = g_sin[s * 64 + j0];
            float c1 = g_cos[s * 64 + j0 + 1], sn1 = g_sin[s * 64 + j0 + 1];
            float a = vals[2*pp], bb = vals[2*pp+1];
            float nx = a * c0 - bb * sn0;
            float ny = bb * c1 + a * sn1;
            if (part == 0) { nx *= QSCALE; ny *= QSCALE; }
            vals[2*pp] = nx; vals[2*pp+1] = ny;
        }
    }
    uint2 uh, ul;
    split2(vals[0], vals[1], uh.x, ul.x);
    split2(vals[2], vals[3], uh.y, ul.y);
    *(uint2*)(g_qkvh + (size_t)row * QKV_N + c4) = uh;
    *(uint2*)(g_qkvl + (size_t)row * QKV_N + c4) = ul;
}

// ---------------- HMMA split-bf16 GEMM (persistent CTAs + raster swizzle) ----------------
#define GBK 32
#define APITCH 80
#define TILE_B (128*APITCH)
#define STAGE_B (4*TILE_B)
#define GEMM_SMEM (2*STAGE_B)

__global__ __launch_bounds__(256, 2) void gemm_hmma(
    const __nv_bfloat16* __restrict__ Ahi, const __nv_bfloat16* __restrict__ Alo,
    const __nv_bfloat16* __restrict__ Bhi, const __nv_bfloat16* __restrict__ Blo,
    float* __restrict__ C, int N, int K, int ntiles, int nbx)
{
    extern __shared__ char smem[];
    const uint32_t sb = smem_u32(smem);
    const int t    = threadIdx.x;
    const int lane = t & 31;
    const int warp = t >> 5;
    const int wm   = warp & 3;
    const int wn   = warp >> 2;
    const int g    = lane >> 2;
    const int tg   = lane & 3;

    uint32_t aoff[2], boff[4];
#pragma unroll
    for (int i = 0; i < 2; i++)
        aoff[i] = (uint32_t)(wm * 32 + i * 16 + (lane & 15)) * APITCH + (lane >> 4) * 16;
#pragma unroll
    for (int jp = 0; jp < 4; jp++)
        boff[jp] = (uint32_t)(wn * 64 + jp * 16 + ((lane >> 4) & 1) * 8 + (lane & 7)) * APITCH
                 + ((lane >> 3) & 1) * 16;

    const int nst = K / GBK;
    const int gsz = 8 * nbx;

#define ISSUE_STAGE(S, BUF) do { \
        int _k0 = (S) * GBK; \
        uint32_t _dst = sb + (BUF) * STAGE_B; \
        const __nv_bfloat16* _srcs[4] = {Ahi, Alo, Bhi, Blo}; \
        const int _r0[4] = {m0, m0, n0, n0}; \
        _Pragma("unroll") \
        for (int _m = 0; _m < 4; _m++) { \
            _Pragma("unroll") \
            for (int _p = 0; _p < 2; _p++) { \
                int _c = t + _p * 256; \
                int _row = _c >> 2, _j = _c & 3; \
                const void* _gp = _srcs[_m] + (size_t)(_r0[_m] + _row) * K + _k0 + _j * 8; \
                uint32_t _sp = _dst + _m * TILE_B + _row * APITCH + _j * 16; \
                asm volatile("cp.async.cg.shared.global [%0], [%1], 16;" :: "r"(_sp), "l"(_gp)); \
            } \
        } \
        asm volatile("cp.async.commit_group;" ::: "memory"); \
    } while (0)

    for (int tile = blockIdx.x; tile < ntiles; tile += gridDim.x) {
        // raster swizzle: 8 m-rows per super-group, sweep n within group
        int grp = tile / gsz;
        int rem = tile - grp * gsz;
        const int m0 = (grp * 8 + (rem & 7)) * 128;
        const int n0 = (rem >> 3) * 128;

        float c[2][8][4];
#pragma unroll
        for (int i = 0; i < 2; i++)
#pragma unroll
            for (int j = 0; j < 8; j++)
#pragma unroll
                for (int q = 0; q < 4; q++) c[i][j][q] = 0.f;

        ISSUE_STAGE(0, 0);

        for (int s = 0; s < nst; s++) {
            const int buf = s & 1;
            if (s + 1 < nst) {
                ISSUE_STAGE(s + 1, (s + 1) & 1);
                asm volatile("cp.async.wait_group 1;" ::: "memory");
            } else {
                asm volatile("cp.async.wait_group 0;" ::: "memory");
            }
            __syncthreads();

            const uint32_t sAh = sb + buf * STAGE_B;
            const uint32_t sAl = sAh + TILE_B;
            const uint32_t sBh = sAl + TILE_B;
            const uint32_t sBl = sBh + TILE_B;

#pragma unroll
            for (int ks = 0; ks < 2; ks++) {
                const uint32_t ko = ks * 32;
                uint32_t ah[2][4], al[2][4];
                ldsm_x4(ah[0], sAh + aoff[0] + ko);
                ldsm_x4(ah[1], sAh + aoff[1] + ko);
                ldsm_x4(al[0], sAl + aoff[0] + ko);
                ldsm_x4(al[1], sAl + aoff[1] + ko);
#pragma unroll
                for (int jp = 0; jp < 4; jp++) {
                    uint32_t bh[4], bl[4];
                    ldsm_x4(bh, sBh + boff[jp] + ko);
                    ldsm_x4(bl, sBl + boff[jp] + ko);
#pragma unroll
                    for (int jj = 0; jj < 2; jj++) {
                        int j = jp * 2 + jj;
#pragma unroll
                        for (int i = 0; i < 2; i++) {
                            mma16816(c[i][j], ah[i], bh[2*jj], bh[2*jj+1]);
                            mma16816(c[i][j], ah[i], bl[2*jj], bl[2*jj+1]);
                            mma16816(c[i][j], al[i], bh[2*jj], bh[2*jj+1]);
                        }
                    }
                }
            }
            __syncthreads();
        }

#pragma unroll
        for (int i = 0; i < 2; i++) {
#pragma unroll
            for (int j = 0; j < 8; j++) {
                int row = m0 + wm * 32 + i * 16 + g;
                int col = n0 + wn * 64 + j * 8 + tg * 2;
                float* p = C + (size_t)row * N + col;
                float2 v0; v0.x = c[i][j][0]; v0.y = c[i][j][1];
                float2 v1; v1.x = c[i][j][2]; v1.y = c[i][j][3];
                *(float2*)p = v0;
                *(float2*)(p + (size_t)8 * N) = v1;
            }
        }
    }
#undef ISSUE_STAGE
}

// ---------------- HMMA windowed flash attention (cp.async bf16 tiles) ----------------
#define AQP 272

struct AttnSm3 {
    char qh[128 * AQP];
    char ql[128 * AQP];
    char kv[2][4][64 * AQP];    // [buf][kh,kl,vh,vl]
};

__global__ __launch_bounds__(256) void attn_mma_kernel(__nv_bfloat16* __restrict__ oh,
                                                       __nv_bfloat16* __restrict__ ol) {
    extern __shared__ char smraw[];
    AttnSm3* sm = (AttnSm3*)smraw;
    const int t    = threadIdx.x;
    const int lane = t & 31;
    const int warp = t >> 5;
    const int q0   = blockIdx.x * 128;
    const int h    = blockIdx.y;
    const int b    = blockIdx.z;
    const int w    = g_window;

    const __nv_bfloat16* qkvh = g_qkvh;
    const __nv_bfloat16* qkvl = g_qkvl;
    const size_t rowbase = (size_t)(b * S_LEN);

#pragma unroll
    for (int p = 0; p < 16; p++) {
        int seg = t + p * 256;
        int mat = seg >> 11;
        int rem = seg & 2047;
        int r = rem >> 4, ch = rem & 15;
        const __nv_bfloat16* src = (mat ? qkvl : qkvh)
            + (rowbase + q0 + r) * QKV_N + h * HDIM + ch * 8;
        uint32_t dst = smem_u32(mat ? sm->ql : sm->qh) + r * AQP + ch * 16;
        asm volatile("cp.async.cg.shared.global [%0], [%1], 16;" :: "r"(dst), "l"(src));
    }
    asm volatile("cp.async.commit_group;" ::: "memory");

#define ISSUE_KV(KC, BUF) do { \
        _Pragma("unroll") \
        for (int _p = 0; _p < 16; _p++) { \
            int _seg = t + _p * 256; \
            int _mat = _seg >> 10; \
            int _rem = _seg & 1023; \
            int _r = _rem >> 4, _ch = _rem & 15; \
            const __nv_bfloat16* _src = ((_mat & 1) ? qkvl : qkvh) \
                + (rowbase + (KC) + _r) * QKV_N + ((_mat < 2) ? EMB : 2 * EMB) + h * HDIM + _ch * 8; \
            uint32_t _dst = smem_u32(sm->kv[BUF][_mat]) + _r * AQP + _ch * 16; \
            asm volatile("cp.async.cg.shared.global [%0], [%1], 16;" :: "r"(_dst), "l"(_src)); \
        } \
        asm volatile("cp.async.commit_group;" ::: "memory"); \
    } while (0)

    int lo_k = q0 - w + 1; if (lo_k < 0) lo_k = 0;
    const int kc0 = lo_k & ~63;
    const int nch = ((q0 + 127 - kc0) >> 6) + 1;

    ISSUE_KV(kc0, 0);

    const uint32_t qbh = smem_u32(sm->qh);
    const uint32_t qbl = smem_u32(sm->ql);
    const uint32_t aoff = (uint32_t)(warp * 16 + (lane & 15)) * AQP + (lane >> 4) * 16;

    uint32_t qfh[8][4], qfl[8][4];

    float o[16][4];
#pragma unroll
    for (int i = 0; i < 16; i++)
#pragma unroll
        for (int q = 0; q < 4; q++) o[i][q] = 0.f;
    float m0 = -1e30f, m1 = -1e30f, l0 = 0.f, l1 = 0.f;

    const int g  = lane >> 2;
    const int tg = lane & 3;
    const int gq0 = q0 + warp * 16 + g;
    const int gq1 = gq0 + 8;

    for (int sidx = 0; sidx < nch; sidx++) {
        const int kc  = kc0 + sidx * 64;
        const int buf = sidx & 1;
        if (sidx + 1 < nch) {
            ISSUE_KV(kc + 64, buf ^ 1);
            asm volatile("cp.async.wait_group 1;" ::: "memory");
        } else {
            asm volatile("cp.async.wait_group 0;" ::: "memory");
        }
        __syncthreads();

        if (sidx == 0) {
#pragma unroll
            for (int kg = 0; kg < 8; kg++) {
                ldsm_x4(qfh[kg], qbh + aoff + kg * 32);
                ldsm_x4(qfl[kg], qbl + aoff + kg * 32);
            }
        }

        const uint32_t kbh = smem_u32(sm->kv[buf][0]);
        const uint32_t kbl = smem_u32(sm->kv[buf][1]);
        const uint32_t vbh = smem_u32(sm->kv[buf][2]);
        const uint32_t vbl = smem_u32(sm->kv[buf][3]);

        float s[8][4];
#pragma unroll
        for (int i = 0; i < 8; i++)
#pragma unroll
            for (int q = 0; q < 4; q++) s[i][q] = 0.f;

#pragma unroll
        for (int kg = 0; kg < 8; kg++) {
#pragma unroll
            for (int nf2 = 0; nf2 < 4; nf2++) {
                uint32_t boff = (uint32_t)(nf2 * 16 + ((lane >> 4) & 1) * 8 + (lane & 7)) * AQP
                              + ((lane >> 3) & 1) * 16 + kg * 32;
                uint32_t bh[4], bl[4];
                ldsm_x4(bh, kbh + boff);
                ldsm_x4(bl, kbl + boff);
#pragma unroll
                for (int jj = 0; jj < 2; jj++) {
                    mma16816(s[nf2*2+jj], qfh[kg], bh[2*jj], bh[2*jj+1]);
                    mma16816(s[nf2*2+jj], qfh[kg], bl[2*jj], bl[2*jj+1]);
                    mma16816(s[nf2*2+jj], qfl[kg], bh[2*jj], bh[2*jj+1]);
                }
            }
        }

        float mn0 = m0, mn1 = m1;
#pragma unroll
        for (int nf = 0; nf < 8; nf++) {
            int gk0 = kc + nf * 8 + tg * 2;
            int gk1 = gk0 + 1;
            bool k00 = (gk0 <= gq0) && (gk0 > gq0 - w);
            bool k01 = (gk1 <= gq0) && (gk1 > gq0 - w);
            bool k10 = (gk0 <= gq1) && (gk0 > gq1 - w);
            bool k11 = (gk1 <= gq1) && (gk1 > gq1 - w);
            mn0 = fmaxf(mn0, k00 ? s[nf][0] : -1e30f);
            mn0 = fmaxf(mn0, k01 ? s[nf][1] : -1e30f);
            mn1 = fmaxf(mn1, k10 ? s[nf][2] : -1e30f);
            mn1 = fmaxf(mn1, k11 ? s[nf][3] : -1e30f);
        }
        mn0 = fmaxf(mn0, __shfl_xor_sync(0xFFFFFFFFu, mn0, 1));
        mn0 = fmaxf(mn0, __shfl_xor_sync(0xFFFFFFFFu, mn0, 2));
        mn1 = fmaxf(mn1, __shfl_xor_sync(0xFFFFFFFFu, mn1, 1));
        mn1 = fmaxf(mn1, __shfl_xor_sync(0xFFFFFFFFu, mn1, 2));
        float sc0 = __expf(m0 - mn0);
        float sc1 = __expf(m1 - mn1);
        float ls0 = 0.f, ls1 = 0.f;
#pragma unroll
        for (int nf = 0; nf < 8; nf++) {
            int gk0 = kc + nf * 8 + tg * 2;
            int gk1 = gk0 + 1;
            bool k00 = (gk0 <= gq0) && (gk0 > gq0 - w);
            bool k01 = (gk1 <= gq0) && (gk1 > gq0 - w);
            bool k10 = (gk0 <= gq1) && (gk0 > gq1 - w);
            bool k11 = (gk1 <= gq1) && (gk1 > gq1 - w);
            float p00 = k00 ? __expf(s[nf][0] - mn0) : 0.f;
            float p01 = k01 ? __expf(s[nf][1] - mn0) : 0.f;
            float p10 = k10 ? __expf(s[nf][2] - mn1) : 0.f;
            float p11 = k11 ? __expf(s[nf][3] - mn1) : 0.f;
            s[nf][0] = p00; s[nf][1] = p01; s[nf][2] = p10; s[nf][3] = p11;
            ls0 += p00 + p01;
            ls1 += p10 + p11;
        }
        ls0 += __shfl_xor_sync(0xFFFFFFFFu, ls0, 1);
        ls0 += __shfl_xor_sync(0xFFFFFFFFu, ls0, 2);
        ls1 += __shfl_xor_sync(0xFFFFFFFFu, ls1, 1);
        ls1 += __shfl_xor_sync(0xFFFFFFFFu, ls1, 2);
        l0 = l0 * sc0 + ls0;
        l1 = l1 * sc1 + ls1;
        m0 = mn0; m1 = mn1;

#pragma unroll
        for (int i = 0; i < 16; i++) {
            o[i][0] *= sc0; o[i][1] *= sc0;
            o[i][2] *= sc1; o[i][3] *= sc1;
        }

#pragma unroll
        for (int kg2 = 0; kg2 < 4; kg2++) {
            uint32_t ah[4], al[4];
            split2(s[2*kg2][0],   s[2*kg2][1],   ah[0], al[0]);
            split2(s[2*kg2][2],   s[2*kg2][3],   ah[1], al[1]);
            split2(s[2*kg2+1][0], s[2*kg2+1][1], ah[2], al[2]);
            split2(s[2*kg2+1][2], s[2*kg2+1][3], ah[3], al[3]);
#pragma unroll
            for (int nf16 = 0; nf16 < 8; nf16++) {
                uint32_t voff = (uint32_t)(kg2 * 16 + ((lane >> 3) & 1) * 8 + (lane & 7)) * AQP
                              + (uint32_t)(nf16 * 16 + (lane >> 4) * 8) * 2;
                uint32_t bvh[4], bvl[4];
                ldsm_x4_t(bvh, vbh + voff);
                ldsm_x4_t(bvl, vbl + voff);
                mma16816(o[2*nf16],   ah, bvh[0], bvh[1]);
                mma16816(o[2*nf16],   ah, bvl[0], bvl[1]);
                mma16816(o[2*nf16],   al, bvh[0], bvh[1]);
                mma16816(o[2*nf16+1], ah, bvh[2], bvh[3]);
                mma16816(o[2*nf16+1], ah, bvl[2], bvl[3]);
                mma16816(o[2*nf16+1], al, bvh[2], bvh[3]);
            }
        }
        __syncthreads();
    }
#undef ISSUE_KV

    float inv0 = 1.f / l0;
    float inv1 = 1.f / l1;
    size_t row0 = (size_t)(b * S_LEN + q0 + warp * 16 + g);
    size_t row1 = row0 + 8;
#pragma unroll
    for (int nf = 0; nf < 16; nf++) {
        int col = h * HDIM + nf * 8 + tg * 2;
        uint32_t hh, ll;
        split2(o[nf][0] * inv0, o[nf][1] * inv0, hh, ll);
        *(uint32_t*)(oh + row0 * EMB + col) = hh;
        *(uint32_t*)(ol + row0 * EMB + col) = ll;
        split2(o[nf][2] * inv1, o[nf][3] * inv1, hh, ll);
        *(uint32_t*)(oh + row1 * EMB + col) = hh;
        *(uint32_t*)(ol + row1 * EMB + col) = ll;
    }
}

// ---------------- launcher ----------------
extern "C" void kernel_launch(void* const* d_in, const int* in_sizes, int n_in,
                              void* d_out, int out_size)
{
    const float* x     = (const float*)d_in[0];
    const float* w_qkv = (const float*)d_in[1];
    const float* w_out = (const float*)d_in[2];
    const float* w_c1  = (const float*)d_in[3];
    const float* w_c2  = (const float*)d_in[4];
    float* out = (float*)d_out;

    static int nsm = 0;
    if (!nsm) {
        cudaDeviceGetAttribute(&nsm, cudaDevAttrMultiProcessorCount, 0);
        cudaFuncSetAttribute(attn_mma_kernel, cudaFuncAttributeMaxDynamicSharedMemorySize,
                             (int)sizeof(AttnSm3));
        cudaFuncSetAttribute(gemm_hmma, cudaFuncAttributeMaxDynamicSharedMemorySize,
                             GEMM_SMEM);
    }
    const int nslots = 2 * nsm;

    void* qkvp = 0; cudaGetSymbolAddress(&qkvp, g_qkv);
    void* ahp  = 0; cudaGetSymbolAddress(&ahp,  g_ah);
    void* alp  = 0; cudaGetSymbolAddress(&alp,  g_al);
    void* bhp  = 0; cudaGetSymbolAddress(&bhp,  g_bh);
    void* blp  = 0; cudaGetSymbolAddress(&blp,  g_bl);

    __nv_bfloat16* ah = (__nv_bfloat16*)ahp;
    __nv_bfloat16* al = (__nv_bfloat16*)alp;
    __nv_bfloat16* bh = (__nv_bfloat16*)bhp;
    __nv_bfloat16* bl = (__nv_bfloat16*)blp;

    // launches 1-3: inputs for GEMM1 (gemm1 is the 4th launch -> ncu captures it)
    split_kernel<<<(MROWS * EMB / 4 + 255) / 256, 256>>>(x, ah, al, MROWS * EMB / 4);
    split_kernel<<<(QKV_N * EMB / 4 + 255) / 256, 256>>>(w_qkv, bh, bl, QKV_N * EMB / 4);
    rope_table_kernel<<<512, 256>>>();

    // GEMM1: qkv = x @ w_qkv^T (fp32 out), persistent CTAs  [4th launch]
    {
        int ntiles = (QKV_N / 128) * (MROWS / 128);   // 1536
        int grid = ntiles < nslots ? ntiles : nslots;
        gemm_hmma<<<grid, 256, GEMM_SMEM>>>(
            ah, al, bh, bl, (float*)qkvp, QKV_N, EMB, ntiles, QKV_N / 128);
    }

    stats_kernel<<<dim3(8, 8, 2), 256>>>(x);
    window_kernel<<<1, 512>>>(w_c1, w_c2);

    // single pass: rope + q-scale + split qkv -> bf16 hi/lo
    qkv_rope_split_kernel<<<(MROWS * QKV_N / 4) / 256, 256>>>();

    // attention reads pre-split qkv; writes bf16 split output into ah/al
    attn_mma_kernel<<<dim3(S_LEN / 128, HEADS, B_SZ), 256, sizeof(AttnSm3)>>>(ah, al);

    // GEMM2: out = attn @ w_out^T, persistent CTAs
    split_kernel<<<(EMB * EMB / 4 + 255) / 256, 256>>>(w_out, bh, bl, EMB * EMB / 4);
    {
        int ntiles = (EMB / 128) * (MROWS / 128);     // 512
        int grid = ntiles < nslots ? ntiles : nslots;
        gemm_hmma<<<grid, 256, GEMM_SMEM>>>(
            ah, al, bh, bl, out, EMB, EMB, ntiles, EMB / 128);
    }
}

// round 17
// speedup vs baseline: 1.0428x; 1.0428x over previous
#include <cuda_runtime.h>
#include <cuda_bf16.h>
#include <math.h>
#include <stdint.h>

#define EMB     2048
#define S_LEN   2048
#define B_SZ    2
#define HEADS   16
#define HDIM    128
#define QKV_N   (3*EMB)
#define MROWS   (B_SZ*S_LEN)

// ---------------- scratch ----------------
__device__ float          g_qkv[25165824];      // 4096 x 6144 fp32 (GEMM1 out)
__device__ __nv_bfloat16  g_qkvh[25165824];     // rope'd+split qkv hi
__device__ __nv_bfloat16  g_qkvl[25165824];     // lo
__device__ __nv_bfloat16  g_ah[8388608];        // A hi (x / attn-out)
__device__ __nv_bfloat16  g_al[8388608];        // A lo
__device__ __nv_bfloat16  g_bh[12582912];       // B hi (w_qkv / w_out)
__device__ __nv_bfloat16  g_bl[12582912];       // B lo
__device__ float  g_cos[S_LEN*64];
__device__ float  g_sin[S_LEN*64];
__device__ float  g_colpart[B_SZ*8*EMB];
__device__ double g_psum[128];
__device__ double g_psq[128];
__device__ int    g_window;

#define QSCALE 0.08838834764831845f

__device__ __forceinline__ uint32_t smem_u32(const void* p) {
    uint32_t a;
    asm("{ .reg .u64 t; cvta.to.shared.u64 t, %1; cvt.u32.u64 %0, t; }" : "=r"(a) : "l"(p));
    return a;
}
__device__ __forceinline__ void ldsm_x4(uint32_t* r, uint32_t addr) {
    asm volatile("ldmatrix.sync.aligned.m8n8.x4.shared.b16 {%0,%1,%2,%3}, [%4];"
        : "=r"(r[0]), "=r"(r[1]), "=r"(r[2]), "=r"(r[3]) : "r"(addr));
}
__device__ __forceinline__ void ldsm_x4_t(uint32_t* r, uint32_t addr) {
    asm volatile("ldmatrix.sync.aligned.m8n8.x4.trans.shared.b16 {%0,%1,%2,%3}, [%4];"
        : "=r"(r[0]), "=r"(r[1]), "=r"(r[2]), "=r"(r[3]) : "r"(addr));
}
__device__ __forceinline__ void mma16816(float* c, const uint32_t* a, uint32_t b0, uint32_t b1) {
    asm volatile("mma.sync.aligned.m16n8k16.row.col.f32.bf16.bf16.f32 "
        "{%0,%1,%2,%3}, {%4,%5,%6,%7}, {%8,%9}, {%0,%1,%2,%3};"
        : "+f"(c[0]), "+f"(c[1]), "+f"(c[2]), "+f"(c[3])
        : "r"(a[0]), "r"(a[1]), "r"(a[2]), "r"(a[3]), "r"(b0), "r"(b1));
}
__device__ __forceinline__ void split2(float x, float y, uint32_t& hi, uint32_t& lo) {
    __nv_bfloat16 hx = __float2bfloat16(x);
    __nv_bfloat16 hy = __float2bfloat16(y);
    __nv_bfloat162 h2 = __halves2bfloat162(hx, hy);
    __nv_bfloat162 l2 = __halves2bfloat162(
        __float2bfloat16(x - __bfloat162float(hx)),
        __float2bfloat16(y - __bfloat162float(hy)));
    hi = *(uint32_t*)&h2;
    lo = *(uint32_t*)&l2;
}

// ---------------- small kernels ----------------
__global__ void rope_table_kernel() {
    int idx = blockIdx.x * blockDim.x + threadIdx.x;
    if (idx >= S_LEN * 64) return;
    int s = idx >> 6, j = idx & 63;
    double inf = exp(-((double)j) * (9.210340371976184 / 64.0));
    double sp, cp;
    sincos((double)s * inf, &sp, &cp);
    g_cos[idx] = (float)cp;
    g_sin[idx] = (float)sp;
}

__global__ void stats_kernel(const float* __restrict__ x) {
    __shared__ double sd[256];
    int t = threadIdx.x;
    int e = blockIdx.x * 256 + t;
    int b = blockIdx.z;
    const float* p = x + ((size_t)(b * S_LEN + blockIdx.y * 256)) * EMB + e;
    float cs = 0.f;
    double ds = 0.0, dq = 0.0;
#pragma unroll 4
    for (int i = 0; i < 256; i++) {
        float v = p[(size_t)i * EMB];
        cs += v;
        ds += (double)v;
        dq += (double)v * (double)v;
    }
    g_colpart[(b * 8 + blockIdx.y) * EMB + e] = cs;
    sd[t] = ds; __syncthreads();
    for (int o = 128; o > 0; o >>= 1) { if (t < o) sd[t] += sd[t + o]; __syncthreads(); }
    double tot = sd[0]; __syncthreads();
    sd[t] = dq; __syncthreads();
    for (int o = 128; o > 0; o >>= 1) { if (t < o) sd[t] += sd[t + o]; __syncthreads(); }
    if (t == 0) {
        int bi = b * 64 + blockIdx.y * 8 + blockIdx.x;
        g_psum[bi] = tot;
        g_psq[bi]  = sd[0];
    }
}

__global__ void window_kernel(const float* __restrict__ w_c1, const float* __restrict__ w_c2) {
    __shared__ float  xm[2 * EMB];
    __shared__ float  red[512];
    __shared__ double dred[64];
    __shared__ float  varn[2];
    __shared__ float  lgv[2];
    int t = threadIdx.x;

    for (int idx = t; idx < 2 * EMB; idx += 512) {
        int b = idx >> 11, e = idx & 2047;
        float s = 0.f;
#pragma unroll
        for (int c = 0; c < 8; c++) s += g_colpart[(b * 8 + c) * EMB + e];
        xm[idx] = s * (1.0f / (float)S_LEN);
    }

    for (int b = 0; b < 2; b++) {
        __syncthreads();
        if (t < 64) dred[t] = g_psum[b * 64 + t];
        __syncthreads();
        for (int o = 32; o > 0; o >>= 1) { if (t < o) dred[t] += dred[t + o]; __syncthreads(); }
        double sum = dred[0];
        __syncthreads();
        if (t < 64) dred[t] = g_psq[b * 64 + t];
        __syncthreads();
        for (int o = 32; o > 0; o >>= 1) { if (t < o) dred[t] += dred[t + o]; __syncthreads(); }
        if (t == 0) {
            double N = (double)S_LEN * (double)EMB;
            float v = (float)((dred[0] - sum * sum / N) / (N - 1.0));
            varn[b] = 1.0f / (1.0f + expf(-(v * 10.0f - 5.0f)));
        }
    }
    __syncthreads();

    float acc0 = 0.f, acc1 = 0.f;
    const float* wr = w_c1 + (size_t)t * EMB;
    for (int e = 0; e < EMB; e++) {
        float w = wr[e];
        acc0 = fmaf(xm[e], w, acc0);
        acc1 = fmaf(xm[EMB + e], w, acc1);
    }
    float w2 = w_c2[t];
    float h0 = acc0 / (1.0f + expf(-acc0));
    float h1 = acc1 / (1.0f + expf(-acc1));

    red[t] = h0 * w2; __syncthreads();
    for (int o = 256; o > 0; o >>= 1) { if (t < o) red[t] += red[t + o]; __syncthreads(); }
    if (t == 0) lgv[0] = red[0];
    __syncthreads();
    red[t] = h1 * w2; __syncthreads();
    for (int o = 256; o > 0; o >>= 1) { if (t < o) red[t] += red[t + o]; __syncthreads(); }
    if (t == 0) {
        lgv[1] = red[0];
        float l0 = 1.0f / (1.0f + expf(-lgv[0]));
        float l1 = 1.0f / (1.0f + expf(-lgv[1]));
        float wf0 = 64.0f + 0.5f * (varn[0] + l0) * 192.0f;
        float wf1 = 64.0f + 0.5f * (varn[1] + l1) * 192.0f;
        int win = (int)(0.5f * (wf0 + wf1));
        if (win > S_LEN) win = S_LEN;
        if (win < 64) win = 64;
        g_window = win;
    }
}

__global__ void split_kernel(const float* __restrict__ src,
                             __nv_bfloat16* __restrict__ hi,
                             __nv_bfloat16* __restrict__ lo, int n4) {
    int i = blockIdx.x * blockDim.x + threadIdx.x;
    if (i >= n4) return;
    float4 v = ((const float4*)src)[i];
    uint32_t h0, l0, h1, l1;
    split2(v.x, v.y, h0, l0);
    split2(v.z, v.w, h1, l1);
    uint2* hp = (uint2*)hi;
    uint2* lp = (uint2*)lo;
    uint2 a; a.x = h0; a.y = h1; hp[i] = a;
    a.x = l0; a.y = l1; lp[i] = a;
}

// rope + q-scale + bf16 hi/lo split over the whole qkv buffer (one pass)
__global__ void qkv_rope_split_kernel() {
    int idx = blockIdx.x * blockDim.x + threadIdx.x;   // one float4 each
    int row = idx / (QKV_N / 4);
    int c4  = (idx % (QKV_N / 4)) * 4;
    float4 v = *(const float4*)(g_qkv + (size_t)row * QKV_N + c4);
    float vals[4] = {v.x, v.y, v.z, v.w};
    int part = c4 >> 11;                 // 0=q, 1=k, 2=v
    if (part < 2) {
        int s = row & (S_LEN - 1);
        int d = c4 & 127;
#pragma unroll
        for (int pp = 0; pp < 2; pp++) {
            int j0 = (d + 2 * pp) & 63;
            float c0 = g_cos[s * 64 + j0],     sn0 = g_sin[s * 64 + j0];
            float c1 = g_cos[s * 64 + j0 + 1], sn1 = g_sin[s * 64 + j0 + 1];
            float a = vals[2*pp], bb = vals[2*pp+1];
            float nx = a * c0 - bb * sn0;
            float ny = bb * c1 + a * sn1;
            if (part == 0) { nx *= QSCALE; ny *= QSCALE; }
            vals[2*pp] = nx; vals[2*pp+1] = ny;
        }
    }
    uint2 uh, ul;
    split2(vals[0], vals[1], uh.x, ul.x);
    split2(vals[2], vals[3], uh.y, ul.y);
    *(uint2*)(g_qkvh + (size_t)row * QKV_N + c4) = uh;
    *(uint2*)(g_qkvl + (size_t)row * QKV_N + c4) = ul;
}

// ---------------- HMMA split-bf16 GEMM (R15-identical: non-persistent, raster swizzle) ----------------
#define GBK 32
#define APITCH 80
#define TILE_B (128*APITCH)
#define STAGE_B (4*TILE_B)
#define GEMM_SMEM (2*STAGE_B)

__global__ __launch_bounds__(256, 2) void gemm_hmma(
    const __nv_bfloat16* __restrict__ Ahi, const __nv_bfloat16* __restrict__ Alo,
    const __nv_bfloat16* __restrict__ Bhi, const __nv_bfloat16* __restrict__ Blo,
    float* __restrict__ C, int N, int K)
{
    extern __shared__ char smem[];
    const uint32_t sb = smem_u32(smem);
    const int t    = threadIdx.x;

    // raster swizzle: 8 m-rows per super-group, sweep n within group
    const int nbx = gridDim.x;
    int lid2 = blockIdx.y * nbx + blockIdx.x;
    int gsz  = 8 * nbx;
    int grp  = lid2 / gsz;
    int rem  = lid2 - grp * gsz;
    const int m0 = (grp * 8 + (rem & 7)) * 128;
    const int n0 = (rem >> 3) * 128;

    const int lane = t & 31;
    const int warp = t >> 5;
    const int wm   = warp & 3;
    const int wn   = warp >> 2;
    const int g    = lane >> 2;
    const int tg   = lane & 3;

    uint32_t aoff[2], boff[4];
#pragma unroll
    for (int i = 0; i < 2; i++)
        aoff[i] = (uint32_t)(wm * 32 + i * 16 + (lane & 15)) * APITCH + (lane >> 4) * 16;
#pragma unroll
    for (int jp = 0; jp < 4; jp++)
        boff[jp] = (uint32_t)(wn * 64 + jp * 16 + ((lane >> 4) & 1) * 8 + (lane & 7)) * APITCH
                 + ((lane >> 3) & 1) * 16;

    float c[2][8][4];
#pragma unroll
    for (int i = 0; i < 2; i++)
#pragma unroll
        for (int j = 0; j < 8; j++)
#pragma unroll
            for (int q = 0; q < 4; q++) c[i][j][q] = 0.f;

    const int nst = K / GBK;

#define ISSUE_STAGE(S, BUF) do { \
        int _k0 = (S) * GBK; \
        uint32_t _dst = sb + (BUF) * STAGE_B; \
        const __nv_bfloat16* _srcs[4] = {Ahi, Alo, Bhi, Blo}; \
        const int _r0[4] = {m0, m0, n0, n0}; \
        _Pragma("unroll") \
        for (int _m = 0; _m < 4; _m++) { \
            _Pragma("unroll") \
            for (int _p = 0; _p < 2; _p++) { \
                int _c = t + _p * 256; \
                int _row = _c >> 2, _j = _c & 3; \
                const void* _gp = _srcs[_m] + (size_t)(_r0[_m] + _row) * K + _k0 + _j * 8; \
                uint32_t _sp = _dst + _m * TILE_B + _row * APITCH + _j * 16; \
                asm volatile("cp.async.cg.shared.global [%0], [%1], 16;" :: "r"(_sp), "l"(_gp)); \
            } \
        } \
        asm volatile("cp.async.commit_group;" ::: "memory"); \
    } while (0)

    ISSUE_STAGE(0, 0);

    for (int s = 0; s < nst; s++) {
        const int buf = s & 1;
        if (s + 1 < nst) {
            ISSUE_STAGE(s + 1, (s + 1) & 1);
            asm volatile("cp.async.wait_group 1;" ::: "memory");
        } else {
            asm volatile("cp.async.wait_group 0;" ::: "memory");
        }
        __syncthreads();

        const uint32_t sAh = sb + buf * STAGE_B;
        const uint32_t sAl = sAh + TILE_B;
        const uint32_t sBh = sAl + TILE_B;
        const uint32_t sBl = sBh + TILE_B;

#pragma unroll
        for (int ks = 0; ks < 2; ks++) {
            const uint32_t ko = ks * 32;
            uint32_t ah[2][4], al[2][4];
            ldsm_x4(ah[0], sAh + aoff[0] + ko);
            ldsm_x4(ah[1], sAh + aoff[1] + ko);
            ldsm_x4(al[0], sAl + aoff[0] + ko);
            ldsm_x4(al[1], sAl + aoff[1] + ko);
#pragma unroll
            for (int jp = 0; jp < 4; jp++) {
                uint32_t bh[4], bl[4];
                ldsm_x4(bh, sBh + boff[jp] + ko);
                ldsm_x4(bl, sBl + boff[jp] + ko);
#pragma unroll
                for (int jj = 0; jj < 2; jj++) {
                    int j = jp * 2 + jj;
#pragma unroll
                    for (int i = 0; i < 2; i++) {
                        mma16816(c[i][j], ah[i], bh[2*jj], bh[2*jj+1]);
                        mma16816(c[i][j], ah[i], bl[2*jj], bl[2*jj+1]);
                        mma16816(c[i][j], al[i], bh[2*jj], bh[2*jj+1]);
                    }
                }
            }
        }
        __syncthreads();
    }
#undef ISSUE_STAGE

#pragma unroll
    for (int i = 0; i < 2; i++) {
#pragma unroll
        for (int j = 0; j < 8; j++) {
            int row = m0 + wm * 32 + i * 16 + g;
            int col = n0 + wn * 64 + j * 8 + tg * 2;
            float* p = C + (size_t)row * N + col;
            float2 v0; v0.x = c[i][j][0]; v0.y = c[i][j][1];
            float2 v1; v1.x = c[i][j][2]; v1.y = c[i][j][3];
            *(float2*)p = v0;
            *(float2*)(p + (size_t)8 * N) = v1;
        }
    }
}

// ---------------- HMMA windowed flash attention ----------------
// per-warp chunk skip (bit-exact: skipped chunks are fully masked) + 1 barrier/chunk
#define AQP 272

struct AttnSm3 {
    char qh[128 * AQP];
    char ql[128 * AQP];
    char kv[2][4][64 * AQP];    // [buf][kh,kl,vh,vl]
};

__global__ __launch_bounds__(256) void attn_mma_kernel(__nv_bfloat16* __restrict__ oh,
                                                       __nv_bfloat16* __restrict__ ol) {
    extern __shared__ char smraw[];
    AttnSm3* sm = (AttnSm3*)smraw;
    const int t    = threadIdx.x;
    const int lane = t & 31;
    const int warp = t >> 5;
    const int q0   = blockIdx.x * 128;
    const int h    = blockIdx.y;
    const int b    = blockIdx.z;
    const int w    = g_window;

    const __nv_bfloat16* qkvh = g_qkvh;
    const __nv_bfloat16* qkvl = g_qkvl;
    const size_t rowbase = (size_t)(b * S_LEN);

    // stage Q via cp.async (own commit group)
#pragma unroll
    for (int p = 0; p < 16; p++) {
        int seg = t + p * 256;
        int mat = seg >> 11;
        int rem = seg & 2047;
        int r = rem >> 4, ch = rem & 15;
        const __nv_bfloat16* src = (mat ? qkvl : qkvh)
            + (rowbase + q0 + r) * QKV_N + h * HDIM + ch * 8;
        uint32_t dst = smem_u32(mat ? sm->ql : sm->qh) + r * AQP + ch * 16;
        asm volatile("cp.async.cg.shared.global [%0], [%1], 16;" :: "r"(dst), "l"(src));
    }
    asm volatile("cp.async.commit_group;" ::: "memory");

#define ISSUE_KV(KC, BUF) do { \
        _Pragma("unroll") \
        for (int _p = 0; _p < 16; _p++) { \
            int _seg = t + _p * 256; \
            int _mat = _seg >> 10; \
            int _rem = _seg & 1023; \
            int _r = _rem >> 4, _ch = _rem & 15; \
            const __nv_bfloat16* _src = ((_mat & 1) ? qkvl : qkvh) \
                + (rowbase + (KC) + _r) * QKV_N + ((_mat < 2) ? EMB : 2 * EMB) + h * HDIM + _ch * 8; \
            uint32_t _dst = smem_u32(sm->kv[BUF][_mat]) + _r * AQP + _ch * 16; \
            asm volatile("cp.async.cg.shared.global [%0], [%1], 16;" :: "r"(_dst), "l"(_src)); \
        } \
        asm volatile("cp.async.commit_group;" ::: "memory"); \
    } while (0)

    int lo_k = q0 - w + 1; if (lo_k < 0) lo_k = 0;
    const int kc0 = lo_k & ~63;
    const int nch = ((q0 + 127 - kc0) >> 6) + 1;

    ISSUE_KV(kc0, 0);

    const uint32_t qbh = smem_u32(sm->qh);
    const uint32_t qbl = smem_u32(sm->ql);
    const uint32_t aoff = (uint32_t)(warp * 16 + (lane & 15)) * AQP + (lane >> 4) * 16;

    uint32_t qfh[8][4], qfl[8][4];

    float o[16][4];
#pragma unroll
    for (int i = 0; i < 16; i++)
#pragma unroll
        for (int q = 0; q < 4; q++) o[i][q] = 0.f;
    float m0 = -1e30f, m1 = -1e30f, l0 = 0.f, l1 = 0.f;

    const int g  = lane >> 2;
    const int tg = lane & 3;
    const int gq0 = q0 + warp * 16 + g;
    const int gq1 = gq0 + 8;

    // this warp's live key range: rows [q0+16*warp, q0+16*warp+15]
    const int wklo = q0 + warp * 16 - w + 1;
    const int wkhi = q0 + warp * 16 + 15;

    for (int sidx = 0; sidx < nch; sidx++) {
        const int kc  = kc0 + sidx * 64;
        const int buf = sidx & 1;

        asm volatile("cp.async.wait_group 0;" ::: "memory");
        __syncthreads();
        if (sidx + 1 < nch) ISSUE_KV(kc + 64, buf ^ 1);

        if (sidx == 0) {
#pragma unroll
            for (int kg = 0; kg < 8; kg++) {
                ldsm_x4(qfh[kg], qbh + aoff + kg * 32);
                ldsm_x4(qfl[kg], qbl + aoff + kg * 32);
            }
        }

        // warp-uniform skip: chunk fully masked for this warp's 16 rows
        if (kc > wkhi || kc + 63 < wklo) continue;

        const uint32_t kbh = smem_u32(sm->kv[buf][0]);
        const uint32_t kbl = smem_u32(sm->kv[buf][1]);
        const uint32_t vbh = smem_u32(sm->kv[buf][2]);
        const uint32_t vbl = smem_u32(sm->kv[buf][3]);

        float s[8][4];
#pragma unroll
        for (int i = 0; i < 8; i++)
#pragma unroll
            for (int q = 0; q < 4; q++) s[i][q] = 0.f;

#pragma unroll
        for (int kg = 0; kg < 8; kg++) {
#pragma unroll
            for (int nf2 = 0; nf2 < 4; nf2++) {
                uint32_t boff = (uint32_t)(nf2 * 16 + ((lane >> 4) & 1) * 8 + (lane & 7)) * AQP
                              + ((lane >> 3) & 1) * 16 + kg * 32;
                uint32_t bh[4], bl[4];
                ldsm_x4(bh, kbh + boff);
                ldsm_x4(bl, kbl + boff);
#pragma unroll
                for (int jj = 0; jj < 2; jj++) {
                    mma16816(s[nf2*2+jj], qfh[kg], bh[2*jj], bh[2*jj+1]);
                    mma16816(s[nf2*2+jj], qfh[kg], bl[2*jj], bl[2*jj+1]);
                    mma16816(s[nf2*2+jj], qfl[kg], bh[2*jj], bh[2*jj+1]);
                }
            }
        }

        float mn0 = m0, mn1 = m1;
#pragma unroll
        for (int nf = 0; nf < 8; nf++) {
            int gk0 = kc + nf * 8 + tg * 2;
            int gk1 = gk0 + 1;
            bool k00 = (gk0 <= gq0) && (gk0 > gq0 - w);
            bool k01 = (gk1 <= gq0) && (gk1 > gq0 - w);
            bool k10 = (gk0 <= gq1) && (gk0 > gq1 - w);
            bool k11 = (gk1 <= gq1) && (gk1 > gq1 - w);
            mn0 = fmaxf(mn0, k00 ? s[nf][0] : -1e30f);
            mn0 = fmaxf(mn0, k01 ? s[nf][1] : -1e30f);
            mn1 = fmaxf(mn1, k10 ? s[nf][2] : -1e30f);
            mn1 = fmaxf(mn1, k11 ? s[nf][3] : -1e30f);
        }
        mn0 = fmaxf(mn0, __shfl_xor_sync(0xFFFFFFFFu, mn0, 1));
        mn0 = fmaxf(mn0, __shfl_xor_sync(0xFFFFFFFFu, mn0, 2));
        mn1 = fmaxf(mn1, __shfl_xor_sync(0xFFFFFFFFu, mn1, 1));
        mn1 = fmaxf(mn1, __shfl_xor_sync(0xFFFFFFFFu, mn1, 2));
        float sc0 = __expf(m0 - mn0);
        float sc1 = __expf(m1 - mn1);
        float ls0 = 0.f, ls1 = 0.f;
#pragma unroll
        for (int nf = 0; nf < 8; nf++) {
            int gk0 = kc + nf * 8 + tg * 2;
            int gk1 = gk0 + 1;
            bool k00 = (gk0 <= gq0) && (gk0 > gq0 - w);
            bool k01 = (gk1 <= gq0) && (gk1 > gq0 - w);
            bool k10 = (gk0 <= gq1) && (gk0 > gq1 - w);
            bool k11 = (gk1 <= gq1) && (gk1 > gq1 - w);
            float p00 = k00 ? __expf(s[nf][0] - mn0) : 0.f;
            float p01 = k01 ? __expf(s[nf][1] - mn0) : 0.f;
            float p10 = k10 ? __expf(s[nf][2] - mn1) : 0.f;
            float p11 = k11 ? __expf(s[nf][3] - mn1) : 0.f;
            s[nf][0] = p00; s[nf][1] = p01; s[nf][2] = p10; s[nf][3] = p11;
            ls0 += p00 + p01;
            ls1 += p10 + p11;
        }
        ls0 += __shfl_xor_sync(0xFFFFFFFFu, ls0, 1);
        ls0 += __shfl_xor_sync(0xFFFFFFFFu, ls0, 2);
        ls1 += __shfl_xor_sync(0xFFFFFFFFu, ls1, 1);
        ls1 += __shfl_xor_sync(0xFFFFFFFFu, ls1, 2);
        l0 = l0 * sc0 + ls0;
        l1 = l1 * sc1 + ls1;
        m0 = mn0; m1 = mn1;

#pragma unroll
        for (int i = 0; i < 16; i++) {
            o[i][0] *= sc0; o[i][1] *= sc0;
            o[i][2] *= sc1; o[i][3] *= sc1;
        }

#pragma unroll
        for (int kg2 = 0; kg2 < 4; kg2++) {
            uint32_t ah[4], al[4];
            split2(s[2*kg2][0],   s[2*kg2][1],   ah[0], al[0]);
            split2(s[2*kg2][2],   s[2*kg2][3],   ah[1], al[1]);
            split2(s[2*kg2+1][0], s[2*kg2+1][1], ah[2], al[2]);
            split2(s[2*kg2+1][2], s[2*kg2+1][3], ah[3], al[3]);
#pragma unroll
            for (int nf16 = 0; nf16 < 8; nf16++) {
                uint32_t voff = (uint32_t)(kg2 * 16 + ((lane >> 3) & 1) * 8 + (lane & 7)) * AQP
                              + (uint32_t)(nf16 * 16 + (lane >> 4) * 8) * 2;
                uint32_t bvh[4], bvl[4];
                ldsm_x4_t(bvh, vbh + voff);
                ldsm_x4_t(bvl, vbl + voff);
                mma16816(o[2*nf16],   ah, bvh[0], bvh[1]);
                mma16816(o[2*nf16],   ah, bvl[0], bvl[1]);
                mma16816(o[2*nf16],   al, bvh[0], bvh[1]);
                mma16816(o[2*nf16+1], ah, bvh[2], bvh[3]);
                mma16816(o[2*nf16+1], ah, bvl[2], bvl[3]);
                mma16816(o[2*nf16+1], al, bvh[2], bvh[3]);
            }
        }
    }
#undef ISSUE_KV

    float inv0 = 1.f / l0;
    float inv1 = 1.f / l1;
    size_t row0 = (size_t)(b * S_LEN + q0 + warp * 16 + g);
    size_t row1 = row0 + 8;
#pragma unroll
    for (int nf = 0; nf < 16; nf++) {
        int col = h * HDIM + nf * 8 + tg * 2;
        uint32_t hh, ll;
        split2(o[nf][0] * inv0, o[nf][1] * inv0, hh, ll);
        *(uint32_t*)(oh + row0 * EMB + col) = hh;
        *(uint32_t*)(ol + row0 * EMB + col) = ll;
        split2(o[nf][2] * inv1, o[nf][3] * inv1, hh, ll);
        *(uint32_t*)(oh + row1 * EMB + col) = hh;
        *(uint32_t*)(ol + row1 * EMB + col) = ll;
    }
}

// ---------------- launcher ----------------
extern "C" void kernel_launch(void* const* d_in, const int* in_sizes, int n_in,
                              void* d_out, int out_size)
{
    const float* x     = (const float*)d_in[0];
    const float* w_qkv = (const float*)d_in[1];
    const float* w_out = (const float*)d_in[2];
    const float* w_c1  = (const float*)d_in[3];
    const float* w_c2  = (const float*)d_in[4];
    float* out = (float*)d_out;

    static int attr_done = 0;
    if (!attr_done) {
        cudaFuncSetAttribute(attn_mma_kernel, cudaFuncAttributeMaxDynamicSharedMemorySize,
                             (int)sizeof(AttnSm3));
        cudaFuncSetAttribute(gemm_hmma, cudaFuncAttributeMaxDynamicSharedMemorySize,
                             GEMM_SMEM);
        attr_done = 1;
    }

    void* qkvp = 0; cudaGetSymbolAddress(&qkvp, g_qkv);
    void* ahp  = 0; cudaGetSymbolAddress(&ahp,  g_ah);
    void* alp  = 0; cudaGetSymbolAddress(&alp,  g_al);
    void* bhp  = 0; cudaGetSymbolAddress(&bhp,  g_bh);
    void* blp  = 0; cudaGetSymbolAddress(&blp,  g_bl);

    __nv_bfloat16* ah = (__nv_bfloat16*)ahp;
    __nv_bfloat16* al = (__nv_bfloat16*)alp;
    __nv_bfloat16* bh = (__nv_bfloat16*)bhp;
    __nv_bfloat16* bl = (__nv_bfloat16*)blp;

    // launches 1-3: inputs for GEMM1 (gemm1 is the 4th launch -> ncu captures it)
    split_kernel<<<(MROWS * EMB / 4 + 255) / 256, 256>>>(x, ah, al, MROWS * EMB / 4);
    split_kernel<<<(QKV_N * EMB / 4 + 255) / 256, 256>>>(w_qkv, bh, bl, QKV_N * EMB / 4);
    rope_table_kernel<<<512, 256>>>();

    // GEMM1: qkv = x @ w_qkv^T (fp32 out)  [4th launch]
    gemm_hmma<<<dim3(QKV_N / 128, MROWS / 128), 256, GEMM_SMEM>>>(
        ah, al, bh, bl, (float*)qkvp, QKV_N, EMB);

    stats_kernel<<<dim3(8, 8, 2), 256>>>(x);
    window_kernel<<<1, 512>>>(w_c1, w_c2);

    // single pass: rope + q-scale + split qkv -> bf16 hi/lo
    qkv_rope_split_kernel<<<(MROWS * QKV_N / 4) / 256, 256>>>();

    // attention reads pre-split qkv; writes bf16 split output into ah/al
    attn_mma_kernel<<<dim3(S_LEN / 128, HEADS, B_SZ), 256, sizeof(AttnSm3)>>>(ah, al);

    // GEMM2: out = attn @ w_out^T
    split_kernel<<<(EMB * EMB / 4 + 255) / 256, 256>>>(w_out, bh, bl, EMB * EMB / 4);
    gemm_hmma<<<dim3(EMB / 128, MROWS / 128), 256, GEMM_SMEM>>>(
        ah, al, bh, bl, out, EMB, EMB);
}